// round 10
// baseline (speedup 1.0000x reference)
#include <cuda_runtime.h>
#include <stdint.h>

#define BATCH 64
#define PIX   784
#define DIMS  10000
#define LVLS  256
#define NCLS  10
#define WPAD  320          // words per row: 10 groups x 32 words
#define NGRP  10           // groups of 1024 dims per row
#define NB    4            // batches per encode block

#define NROWS      (PIX + LVLS)          // 1040
#define NTASK_PACK (NROWS * NGRP)        // 10400
#define NTASK_IDX  ((BATCH * PIX) / 128) // 392
#define NTASK_ALL  (NTASK_PACK + NTASK_IDX)
#define PACK_BLOCKS 592

// Packed bit layout (PERMUTED, identical for pos / lvl / enc):
//   dim d = g*1024 + i*128 + l*4 + j  <->  word (g*32 + l), bit (i*4 + j)

// ---- scratch (static device globals; no allocations) ----
__device__ uint32_t g_pos_bits[PIX  * WPAD];
__device__ uint32_t g_lvl_bits[LVLS * WPAD];
__device__ uint8_t  g_idx[BATCH * PIX];
__device__ float    g_pd[BATCH * NCLS * NGRP];   // per-(b,c,wblock) partial logits

// pixel chunk starts (all multiples of 4) and lengths {100x4, 96x4}
__device__ __constant__ int c_start[8] = {0, 100, 200, 300, 400, 496, 592, 688};
__device__ __constant__ int c_len[8]   = {100, 100, 100, 100, 96, 96, 96, 96};

// ------------------------------------------------------------------
// K0: grid-stride warp-task pack + idx quant (unchanged; at its ceiling).
// ------------------------------------------------------------------
__global__ void __launch_bounds__(256, 4) pack_all(const float* __restrict__ pos,
                                                   const float* __restrict__ lvl,
                                                   const float* __restrict__ x) {
    int lane  = threadIdx.x & 31;
    int gwarp = (blockIdx.x * 256 + threadIdx.x) >> 5;
    const int nwarps = PACK_BLOCKS * 8;

    for (int task = gwarp; task < NTASK_ALL; task += nwarps) {
        if (task < NTASK_PACK) {
            int row = task / NGRP;
            int g   = task - row * NGRP;

            const float* src;
            uint32_t* dst;
            if (row < PIX) { src = pos + (size_t)row * DIMS; dst = g_pos_bits + row * WPAD; }
            else           { src = lvl + (size_t)(row - PIX) * DIMS; dst = g_lvl_bits + (row - PIX) * WPAD; }

            float4 v[8];
            #pragma unroll
            for (int i = 0; i < 8; i++) {
                int e = g * 1024 + i * 128 + lane * 4;
                v[i] = (e < DIMS) ? *(const float4*)(src + e)
                                  : make_float4(1.0f, 1.0f, 1.0f, 1.0f);
            }

            uint32_t w = 0;
            #pragma unroll
            for (int i = 0; i < 8; i++) {
                uint32_t nib = (__float_as_uint(v[i].x) >> 31)
                             | ((__float_as_uint(v[i].y) >> 31) << 1)
                             | ((__float_as_uint(v[i].z) >> 31) << 2)
                             | ((__float_as_uint(v[i].w) >> 31) << 3);
                w |= nib << (i * 4);
            }
            dst[g * 32 + lane] = w;
        } else {
            int t2 = task - NTASK_PACK;
            int base = t2 * 128 + lane * 4;
            float4 v = *(const float4*)(x + base);
            uchar4 o;
            int i0 = __float2int_rn(v.x * 255.0f); o.x = (uint8_t)max(0, min(255, i0));
            int i1 = __float2int_rn(v.y * 255.0f); o.y = (uint8_t)max(0, min(255, i1));
            int i2 = __float2int_rn(v.z * 255.0f); o.z = (uint8_t)max(0, min(255, i2));
            int i3 = __float2int_rn(v.w * 255.0f); o.w = (uint8_t)max(0, min(255, i3));
            *(uchar4*)(g_idx + base) = o;
        }
    }
}

// ------------------------------------------------------------------
// K1: fused bind+bundle + threshold + partial classify, 4 batches/block.
// Grid (10 wblocks, 16 batch-quads), 256 threads. Warp = one pixel chunk,
// each pos word loaded ONCE and reused across 4 batches.
// ------------------------------------------------------------------
__global__ void __launch_bounds__(256) hdc_encode(const float* __restrict__ Wc) {
    __shared__ uint32_t s_lvl[LVLS * 32];      // 32 KB, aliased as s_pl after loop
    __shared__ uint32_t s_enc[NB][32];
    __shared__ float    s_red[NB][8][NCLS];

    int lane   = threadIdx.x & 31;
    int wid    = threadIdx.x >> 5;             // pixel chunk 0..7
    int wblock = blockIdx.x;                   // 0..9
    int bb     = blockIdx.y * NB;              // batch base
    int w = wblock * 32 + lane;

    for (int l = wid; l < LVLS; l += 8)
        s_lvl[l * 32 + lane] = g_lvl_bits[l * WPAD + w];
    __syncthreads();

    int pstart = c_start[wid];
    int nq     = c_len[wid] >> 2;              // 25 or 24 quads
    const uint32_t* posr = g_pos_bits + pstart * WPAD + w;
    const uint8_t*  idx0 = g_idx + (bb + 0) * PIX + pstart;
    const uint8_t*  idx1 = g_idx + (bb + 1) * PIX + pstart;
    const uint8_t*  idx2 = g_idx + (bb + 2) * PIX + pstart;
    const uint8_t*  idx3 = g_idx + (bb + 3) * PIX + pstart;

    // 4 x 7-plane counters (max 100 per column per batch)
    uint32_t cnt[NB][7];
    #pragma unroll
    for (int k = 0; k < NB; k++)
        #pragma unroll
        for (int i = 0; i < 7; i++) cnt[k][i] = 0;

    for (int q = 0; q < nq; q++) {
        // pos words: loaded once, reused for all 4 batches
        uint32_t p0 = posr[(q * 4 + 0) * WPAD];
        uint32_t p1 = posr[(q * 4 + 1) * WPAD];
        uint32_t p2 = posr[(q * 4 + 2) * WPAD];
        uint32_t p3 = posr[(q * 4 + 3) * WPAD];
        uint32_t i4[NB];
        i4[0] = *(const uint32_t*)(idx0 + q * 4);
        i4[1] = *(const uint32_t*)(idx1 + q * 4);
        i4[2] = *(const uint32_t*)(idx2 + q * 4);
        i4[3] = *(const uint32_t*)(idx3 + q * 4);

        #pragma unroll
        for (int k = 0; k < NB; k++) {
            uint32_t x0 = s_lvl[((i4[k]      ) & 255u) * 32 + lane] ^ p0;
            uint32_t x1 = s_lvl[((i4[k] >>  8) & 255u) * 32 + lane] ^ p1;
            uint32_t x2 = s_lvl[((i4[k] >> 16) & 255u) * 32 + lane] ^ p2;
            uint32_t x3 = s_lvl[((i4[k] >> 24)       ) * 32 + lane] ^ p3;

            uint32_t t0  = x0 ^ x1;
            uint32_t l01 = t0 ^ x2;
            uint32_t h01 = (x0 & x1) | (t0 & x2);
            uint32_t t1 = cnt[k][0] ^ l01;
            uint32_t ca = (cnt[k][0] & l01) | (t1 & x3);
            cnt[k][0] = t1 ^ x3;
            uint32_t t2 = cnt[k][1] ^ h01;
            uint32_t cb = (cnt[k][1] & h01) | (t2 & ca);
            cnt[k][1] = t2 ^ ca;
            uint32_t cr = cb, t;
            t = cnt[k][2] & cr; cnt[k][2] ^= cr; cr = t;
            t = cnt[k][3] & cr; cnt[k][3] ^= cr; cr = t;
            t = cnt[k][4] & cr; cnt[k][4] ^= cr; cr = t;
            t = cnt[k][5] & cr; cnt[k][5] ^= cr; cr = t;
            cnt[k][6] ^= cr;
        }
    }
    __syncthreads();                           // done reading s_lvl

    // alias: s_pl[warp][batch][plane][lane] = 8*4*7*32*4 = 28 KB
    uint32_t (*s_pl)[NB][7][32] = (uint32_t (*)[NB][7][32])s_lvl;
    #pragma unroll
    for (int k = 0; k < NB; k++)
        #pragma unroll
        for (int i = 0; i < 7; i++)
            s_pl[wid][k][i][lane] = cnt[k][i];
    __syncthreads();

    // warps 0..3: merge 8 partials for batch (wid), threshold vs 392
    if (wid < NB) {
        int bq = wid;
        uint32_t cur[10];
        #pragma unroll
        for (int i = 0; i < 7; i++) cur[i] = s_pl[0][bq][i][lane];
        #pragma unroll
        for (int i = 7; i < 10; i++) cur[i] = 0;

        #pragma unroll
        for (int k = 1; k < 8; k++) {
            uint32_t carry = 0;
            #pragma unroll
            for (int i = 0; i < 7; i++) {
                uint32_t bv = s_pl[k][bq][i][lane];
                uint32_t a  = cur[i];
                uint32_t t  = a ^ bv;
                cur[i] = t ^ carry;
                carry  = (a & bv) | (t & carry);
            }
            #pragma unroll
            for (int i = 7; i < 10; i++) {
                uint32_t a = cur[i];
                cur[i] = a ^ carry;
                carry  = a & carry;
            }
        }

        // cnt >= 392 (0b0110001000) -> enc = -1
        uint32_t gt = 0, eq = 0xffffffffu;
        #pragma unroll
        for (int i = 9; i >= 0; i--) {
            if ((392 >> i) & 1) { eq &= cur[i]; }
            else { gt |= eq & cur[i]; eq &= ~cur[i]; }
        }
        s_enc[bq][lane] = gt | eq;
    }
    __syncthreads();

    // fused partial classify: thread t covers dims [wblock*1024 + t*4, +4),
    // looped over 4 batches (Wc re-reads are L1 hits).
    int t4 = threadIdx.x;
    int d  = wblock * 1024 + t4 * 4;
    int shift = ((t4 >> 5) & 7) << 2;

    #pragma unroll
    for (int bq = 0; bq < NB; bq++) {
        float acc[NCLS];
        #pragma unroll
        for (int c = 0; c < NCLS; c++) acc[c] = 0.0f;

        if (d < DIMS) {
            uint32_t nib = s_enc[bq][t4 & 31] >> shift;
            uint32_t f0 = (nib        & 1u) << 31;
            uint32_t f1 = ((nib >> 1) & 1u) << 31;
            uint32_t f2 = ((nib >> 2) & 1u) << 31;
            uint32_t f3 = ((nib >> 3) & 1u) << 31;
            #pragma unroll
            for (int c = 0; c < NCLS; c++) {
                float4 v = *(const float4*)(Wc + (size_t)c * DIMS + d);
                float s01 = __uint_as_float(__float_as_uint(v.x) ^ f0)
                          + __uint_as_float(__float_as_uint(v.y) ^ f1);
                float s23 = __uint_as_float(__float_as_uint(v.z) ^ f2)
                          + __uint_as_float(__float_as_uint(v.w) ^ f3);
                acc[c] = s01 + s23;
            }
        }

        #pragma unroll
        for (int c = 0; c < NCLS; c++) {
            float v = acc[c];
            #pragma unroll
            for (int off = 16; off > 0; off >>= 1)
                v += __shfl_down_sync(0xffffffffu, v, off);
            if (lane == 0) s_red[bq][wid][c] = v;
        }
    }
    __syncthreads();

    // warp bq writes batch (bb+bq)'s partials
    if (wid < NB && lane < NCLS) {
        float s = 0.0f;
        #pragma unroll
        for (int k = 0; k < 8; k++) s += s_red[wid][k][lane];
        g_pd[((bb + wid) * NCLS + lane) * NGRP + wblock] = s;
    }
}

// ------------------------------------------------------------------
// K2: reduce partials over wblocks -> out[b][c]
// ------------------------------------------------------------------
__global__ void __launch_bounds__(256) reduce_out(float* __restrict__ out) {
    int tid = blockIdx.x * 256 + threadIdx.x;
    if (tid >= BATCH * NCLS) return;
    const float* p = g_pd + tid * NGRP;
    float s = 0.0f;
    #pragma unroll
    for (int i = 0; i < NGRP; i++) s += p[i];
    out[tid] = s;
}

// ------------------------------------------------------------------
extern "C" void kernel_launch(void* const* d_in, const int* in_sizes, int n_in,
                              void* d_out, int out_size) {
    const float* x   = (const float*)d_in[0];   // [64,28,28]
    const float* pos = (const float*)d_in[1];   // [784,10000]
    const float* lvl = (const float*)d_in[2];   // [256,10000]
    const float* cw  = (const float*)d_in[3];   // [10,10000]
    float* out = (float*)d_out;                 // [64,10]

    pack_all<<<PACK_BLOCKS, 256>>>(pos, lvl, x);
    hdc_encode<<<dim3(NGRP, BATCH / NB), 256>>>(cw);
    reduce_out<<<(BATCH * NCLS + 255) / 256, 256>>>(out);
}

// round 11
// speedup vs baseline: 1.2526x; 1.2526x over previous
#include <cuda_runtime.h>
#include <stdint.h>

#define BATCH 64
#define PIX   784
#define DIMS  10000
#define LVLS  256
#define NCLS  10
#define WPAD  320          // words per row: 10 groups x 32 words
#define NGRP  10           // groups of 1024 dims per row

#define NROWS      (PIX + LVLS)          // 1040
#define NTASK_PACK (NROWS * NGRP)        // 10400
#define NTASK_IDX  ((BATCH * PIX) / 128) // 392
#define NTASK_ALL  (NTASK_PACK + NTASK_IDX)
#define PACK_BLOCKS 592

// Packed bit layout (PERMUTED, identical for pos / lvl / enc):
//   dim d = g*1024 + i*128 + l*4 + j  <->  word (g*32 + l), bit (i*4 + j)

// ---- scratch (static device globals; zero-init, no allocations) ----
__device__ uint32_t g_pos_bits[PIX  * WPAD];
__device__ uint32_t g_lvl_bits[LVLS * WPAD];
__device__ uint8_t  g_idx[BATCH * PIX];
__device__ float    g_pd[BATCH * NCLS * NGRP];   // per-(b,c,wblock) partial logits
__device__ int      g_arrive[BATCH];             // arrival counters (reset each use)

// pixel chunk starts (all multiples of 4) and lengths {100x4, 96x4}
__device__ __constant__ int c_start[8] = {0, 100, 200, 300, 400, 496, 592, 688};
__device__ __constant__ int c_len[8]   = {100, 100, 100, 100, 96, 96, 96, 96};

// ------------------------------------------------------------------
// K0: grid-stride warp-task pack + idx quant (at its measured ceiling).
// ------------------------------------------------------------------
__global__ void __launch_bounds__(256, 4) pack_all(const float* __restrict__ pos,
                                                   const float* __restrict__ lvl,
                                                   const float* __restrict__ x) {
    int lane  = threadIdx.x & 31;
    int gwarp = (blockIdx.x * 256 + threadIdx.x) >> 5;
    const int nwarps = PACK_BLOCKS * 8;

    for (int task = gwarp; task < NTASK_ALL; task += nwarps) {
        if (task < NTASK_PACK) {
            int row = task / NGRP;
            int g   = task - row * NGRP;

            const float* src;
            uint32_t* dst;
            if (row < PIX) { src = pos + (size_t)row * DIMS; dst = g_pos_bits + row * WPAD; }
            else           { src = lvl + (size_t)(row - PIX) * DIMS; dst = g_lvl_bits + (row - PIX) * WPAD; }

            float4 v[8];
            #pragma unroll
            for (int i = 0; i < 8; i++) {
                int e = g * 1024 + i * 128 + lane * 4;
                v[i] = (e < DIMS) ? *(const float4*)(src + e)
                                  : make_float4(1.0f, 1.0f, 1.0f, 1.0f);
            }

            uint32_t w = 0;
            #pragma unroll
            for (int i = 0; i < 8; i++) {
                uint32_t nib = (__float_as_uint(v[i].x) >> 31)
                             | ((__float_as_uint(v[i].y) >> 31) << 1)
                             | ((__float_as_uint(v[i].z) >> 31) << 2)
                             | ((__float_as_uint(v[i].w) >> 31) << 3);
                w |= nib << (i * 4);
            }
            dst[g * 32 + lane] = w;
        } else {
            int t2 = task - NTASK_PACK;
            int base = t2 * 128 + lane * 4;
            float4 v = *(const float4*)(x + base);
            uchar4 o;
            int i0 = __float2int_rn(v.x * 255.0f); o.x = (uint8_t)max(0, min(255, i0));
            int i1 = __float2int_rn(v.y * 255.0f); o.y = (uint8_t)max(0, min(255, i1));
            int i2 = __float2int_rn(v.z * 255.0f); o.z = (uint8_t)max(0, min(255, i2));
            int i3 = __float2int_rn(v.w * 255.0f); o.w = (uint8_t)max(0, min(255, i3));
            *(uchar4*)(g_idx + base) = o;
        }
    }
}

// ------------------------------------------------------------------
// K1: fused bind+bundle + threshold + partial classify + final reduce.
// Grid (10 wblocks, 64 batches), 256 threads. Warp = one pixel chunk.
// Last-arriving block per batch sums the 10 partials (fixed order ->
// deterministic) and writes out, then resets the counter.
// ------------------------------------------------------------------
__global__ void __launch_bounds__(256) hdc_encode(const float* __restrict__ Wc,
                                                  float* __restrict__ out) {
    __shared__ uint32_t s_lvl[LVLS * 32];      // 32 KB (aliased as s_pl)
    __shared__ uint32_t s_enc[32];
    __shared__ float    s_red[8][NCLS];
    __shared__ int      s_last;

    int lane   = threadIdx.x & 31;
    int wid    = threadIdx.x >> 5;             // pixel chunk 0..7
    int wblock = blockIdx.x;                   // 0..9
    int b      = blockIdx.y;                   // 0..63
    int w = wblock * 32 + lane;

    for (int l = wid; l < LVLS; l += 8)
        s_lvl[l * 32 + lane] = g_lvl_bits[l * WPAD + w];
    __syncthreads();

    int pstart = c_start[wid];
    int nq     = c_len[wid] >> 2;              // 25 or 24 quads
    const uint8_t*  idxr = g_idx + b * PIX + pstart;        // 4-aligned
    const uint32_t* posr = g_pos_bits + pstart * WPAD + w;

    // 7-plane counter (max 100 per column)
    uint32_t c0 = 0, c1 = 0, c2 = 0, c3 = 0, c4 = 0, c5 = 0, c6 = 0;

    for (int q = 0; q < nq; q++) {
        uint32_t i4 = *(const uint32_t*)(idxr + q * 4);
        uint32_t x0 = s_lvl[((i4      ) & 255u) * 32 + lane] ^ posr[(q * 4 + 0) * WPAD];
        uint32_t x1 = s_lvl[((i4 >>  8) & 255u) * 32 + lane] ^ posr[(q * 4 + 1) * WPAD];
        uint32_t x2 = s_lvl[((i4 >> 16) & 255u) * 32 + lane] ^ posr[(q * 4 + 2) * WPAD];
        uint32_t x3 = s_lvl[((i4 >> 24)       ) * 32 + lane] ^ posr[(q * 4 + 3) * WPAD];

        uint32_t t0  = x0 ^ x1;
        uint32_t l01 = t0 ^ x2;
        uint32_t h01 = (x0 & x1) | (t0 & x2);
        uint32_t t1 = c0 ^ l01;
        uint32_t ca = (c0 & l01) | (t1 & x3);
        c0 = t1 ^ x3;
        uint32_t t2 = c1 ^ h01;
        uint32_t cb = (c1 & h01) | (t2 & ca);
        c1 = t2 ^ ca;
        uint32_t cr = cb, t;
        t = c2 & cr; c2 ^= cr; cr = t;
        t = c3 & cr; c3 ^= cr; cr = t;
        t = c4 & cr; c4 ^= cr; cr = t;
        t = c5 & cr; c5 ^= cr; cr = t;
        c6 ^= cr;
    }
    __syncthreads();                           // everyone done reading s_lvl

    uint32_t (*s_pl)[7][32] = (uint32_t (*)[7][32])s_lvl;
    s_pl[wid][0][lane] = c0; s_pl[wid][1][lane] = c1;
    s_pl[wid][2][lane] = c2; s_pl[wid][3][lane] = c3;
    s_pl[wid][4][lane] = c4; s_pl[wid][5][lane] = c5;
    s_pl[wid][6][lane] = c6;
    __syncthreads();

    if (wid == 0) {
        uint32_t cur[10];
        #pragma unroll
        for (int i = 0; i < 7; i++) cur[i] = s_pl[0][i][lane];
        #pragma unroll
        for (int i = 7; i < 10; i++) cur[i] = 0;

        #pragma unroll
        for (int k = 1; k < 8; k++) {
            uint32_t carry = 0;
            #pragma unroll
            for (int i = 0; i < 7; i++) {
                uint32_t bv = s_pl[k][i][lane];
                uint32_t a  = cur[i];
                uint32_t t  = a ^ bv;
                cur[i] = t ^ carry;
                carry  = (a & bv) | (t & carry);
            }
            #pragma unroll
            for (int i = 7; i < 10; i++) {
                uint32_t a = cur[i];
                cur[i] = a ^ carry;
                carry  = a & carry;
            }
        }

        // cnt >= 392 (0b0110001000) -> enc = -1
        uint32_t gt = 0, eq = 0xffffffffu;
        #pragma unroll
        for (int i = 9; i >= 0; i--) {
            if ((392 >> i) & 1) { eq &= cur[i]; }
            else { gt |= eq & cur[i]; eq &= ~cur[i]; }
        }
        s_enc[lane] = gt | eq;
    }
    __syncthreads();

    // fused partial classify: thread t covers dims [wblock*1024 + t*4, +4)
    int t4 = threadIdx.x;
    int d  = wblock * 1024 + t4 * 4;
    float acc[NCLS];
    #pragma unroll
    for (int c = 0; c < NCLS; c++) acc[c] = 0.0f;

    if (d < DIMS) {
        uint32_t nib = s_enc[t4 & 31] >> (((t4 >> 5) & 7) << 2);
        uint32_t f0 = (nib        & 1u) << 31;
        uint32_t f1 = ((nib >> 1) & 1u) << 31;
        uint32_t f2 = ((nib >> 2) & 1u) << 31;
        uint32_t f3 = ((nib >> 3) & 1u) << 31;
        #pragma unroll
        for (int c = 0; c < NCLS; c++) {
            float4 v = *(const float4*)(Wc + (size_t)c * DIMS + d);
            float s01 = __uint_as_float(__float_as_uint(v.x) ^ f0)
                      + __uint_as_float(__float_as_uint(v.y) ^ f1);
            float s23 = __uint_as_float(__float_as_uint(v.z) ^ f2)
                      + __uint_as_float(__float_as_uint(v.w) ^ f3);
            acc[c] = s01 + s23;
        }
    }

    #pragma unroll
    for (int c = 0; c < NCLS; c++) {
        float v = acc[c];
        #pragma unroll
        for (int off = 16; off > 0; off >>= 1)
            v += __shfl_down_sync(0xffffffffu, v, off);
        if (lane == 0) s_red[wid][c] = v;
    }
    __syncthreads();

    if (wid == 0 && lane < NCLS) {
        float s = 0.0f;
        #pragma unroll
        for (int k = 0; k < 8; k++) s += s_red[k][lane];
        g_pd[(b * NCLS + lane) * NGRP + wblock] = s;
    }
    __syncthreads();   // ensure partial writes are ordered before the fence/atomic

    // --- last-block reduction for batch b (threadFenceReduction pattern) ---
    if (threadIdx.x == 0) {
        __threadfence();
        int old = atomicAdd(&g_arrive[b], 1);
        s_last = (old == NGRP - 1);
    }
    __syncthreads();

    if (s_last) {
        if (threadIdx.x == 0) __threadfence();   // acquire other blocks' g_pd writes
        __syncthreads();
        if (wid == 0 && lane < NCLS) {
            const float* p = g_pd + (b * NCLS + lane) * NGRP;
            float s = 0.0f;
            #pragma unroll
            for (int i = 0; i < NGRP; i++) s += p[i];   // fixed order -> deterministic
            out[b * NCLS + lane] = s;
        }
        if (threadIdx.x == 0) g_arrive[b] = 0;   // reset for next graph replay
    }
}

// ------------------------------------------------------------------
extern "C" void kernel_launch(void* const* d_in, const int* in_sizes, int n_in,
                              void* d_out, int out_size) {
    const float* x   = (const float*)d_in[0];   // [64,28,28]
    const float* pos = (const float*)d_in[1];   // [784,10000]
    const float* lvl = (const float*)d_in[2];   // [256,10000]
    const float* cw  = (const float*)d_in[3];   // [10,10000]
    float* out = (float*)d_out;                 // [64,10]

    pack_all<<<PACK_BLOCKS, 256>>>(pos, lvl, x);
    hdc_encode<<<dim3(NGRP, BATCH), 256>>>(cw, out);
}